// round 4
// baseline (speedup 1.0000x reference)
#include <cuda_runtime.h>
#include <cuda_bf16.h>
#include <cuda_fp16.h>

#define N_NODES 100000
#define N_EDGES 1600000
#define IN_CH 128
#define HEADS 4
#define OUT_CH 32
#define HO 128
#define NEG_SLOPE 0.2f
#define EPS 1e-10f

#define SCAN_B 512
#define SCAN_NB ((N_NODES + SCAN_B - 1) / SCAN_B)   // 196

// ---------------- scratch ----------------
__device__ __align__(16) __half g_h16[(size_t)N_NODES * HO];   // 25.6 MB
__device__ __align__(16) float g_ssrc[(size_t)N_NODES * HEADS];
__device__ __align__(16) float g_stgt[(size_t)N_NODES * HEADS];
__device__ int g_deg[N_NODES];
__device__ int g_off[N_NODES];
__device__ int g_cursor[N_NODES];
__device__ int g_bsum[SCAN_NB];
__device__ int g_esrc[N_EDGES];
__device__ int g_idx64;

// ---------------- dtype detection for edge_index ----------------
__global__ void detect_kernel(const unsigned int* __restrict__ e) {
    __shared__ int any;
    if (threadIdx.x == 0) any = 0;
    __syncthreads();
    unsigned int v = 0;
    for (int i = threadIdx.x; i < 1024; i += blockDim.x) v |= e[2 * i + 1];
    if (v) any = 1;
    __syncthreads();
    if (threadIdx.x == 0) g_idx64 = (any == 0) ? 1 : 0;
}

__device__ __forceinline__ int load_idx(const void* eidx, int i) {
    if (g_idx64) return (int)((const long long*)eidx)[i];
    return ((const int*)eidx)[i];
}

__global__ void zero_deg_kernel() {
    int i = blockIdx.x * blockDim.x + threadIdx.x;
    if (i < N_NODES) g_deg[i] = 0;
}

__global__ __launch_bounds__(256) void hist_kernel(const void* __restrict__ eidx) {
    int e = blockIdx.x * blockDim.x + threadIdx.x;
    if (e >= N_EDGES) return;
    int tgt = load_idx(eidx, N_EDGES + e);
    atomicAdd(&g_deg[tgt], 1);
}

// ---------------- 3-phase exclusive scan of g_deg -> g_off ----------------
__global__ __launch_bounds__(SCAN_B) void scan1_kernel() {
    __shared__ int sm[SCAN_B];
    int i = blockIdx.x * SCAN_B + threadIdx.x;
    int t = threadIdx.x;
    int v = (i < N_NODES) ? g_deg[i] : 0;
    sm[t] = v;
    __syncthreads();
#pragma unroll
    for (int off = 1; off < SCAN_B; off <<= 1) {
        int a = (t >= off) ? sm[t - off] : 0;
        __syncthreads();
        sm[t] += a;
        __syncthreads();
    }
    if (i < N_NODES) g_off[i] = sm[t] - v;
    if (t == SCAN_B - 1) g_bsum[blockIdx.x] = sm[t];
}

__global__ __launch_bounds__(256) void scan2_kernel() {
    __shared__ int sm[256];
    int t = threadIdx.x;
    int v = (t < SCAN_NB) ? g_bsum[t] : 0;
    sm[t] = v;
    __syncthreads();
#pragma unroll
    for (int off = 1; off < 256; off <<= 1) {
        int a = (t >= off) ? sm[t - off] : 0;
        __syncthreads();
        sm[t] += a;
        __syncthreads();
    }
    if (t < SCAN_NB) g_bsum[t] = sm[t] - v;
}

__global__ __launch_bounds__(SCAN_B) void scan3_kernel() {
    int i = blockIdx.x * SCAN_B + threadIdx.x;
    if (i >= N_NODES) return;
    int o = g_off[i] + g_bsum[blockIdx.x];
    g_off[i] = o;
    g_cursor[i] = o;
}

__global__ __launch_bounds__(256) void scatter_kernel(const void* __restrict__ eidx) {
    int e = blockIdx.x * blockDim.x + threadIdx.x;
    if (e >= N_EDGES) return;
    int src = load_idx(eidx, e);
    int tgt = load_idx(eidx, N_EDGES + e);
    int slot = atomicAdd(&g_cursor[tgt], 1);
    g_esrc[slot] = src;
}

// ---------------- fused GEMM + score kernel ----------------
// BM=128 rows/block, 256 threads. Thread (tx=tid&15, ty=tid>>4):
// rows ty*8..ty*8+7; cols {4tx..4tx+3} U {64+4tx..64+4tx+3}.
// x: LDS.32 broadcast + alu-pipe pack to {v,v}; w: 2x LDS.128 stride-4 chunks.
#define BM 128
#define BK 32
__global__ __launch_bounds__(256) void gemm_kernel(
    const float* __restrict__ x, const float* __restrict__ W,
    const float* __restrict__ att) {
    __shared__ float xs[BM][BK];       // 16 KB
    __shared__ float ws[BK][IN_CH];    // 16 KB
    const int tid = threadIdx.x;
    const int tx = tid & 15;
    const int ty = tid >> 4;
    const int row0 = blockIdx.x * BM;

    // heads for the two column chunks
    const int h0 = tx >> 3;            // 0 or 1
    const int c0 = (tx & 7) * 4;       // col offset within head
    const float* ar0 = att + h0 * (2 * OUT_CH);
    const float* ar1 = att + (h0 + 2) * (2 * OUT_CH);
    float as0[4], at0[4], as1[4], at1[4];
#pragma unroll
    for (int j = 0; j < 4; j++) {
        as0[j] = ar0[c0 + j];          at0[j] = ar0[OUT_CH + c0 + j];
        as1[j] = ar1[c0 + j];          at1[j] = ar1[OUT_CH + c0 + j];
    }

    unsigned long long acc[8][4];
#pragma unroll
    for (int i = 0; i < 8; i++)
#pragma unroll
        for (int j = 0; j < 4; j++) acc[i][j] = 0ull;

    for (int kt = 0; kt < IN_CH / BK; kt++) {
        // x tile: 128 rows x 8 float4
        for (int i = tid; i < BM * (BK / 4); i += 256) {
            int r = i >> 3;
            int cc = i & 7;
            int grow = row0 + r;
            float4 v = make_float4(0.f, 0.f, 0.f, 0.f);
            if (grow < N_NODES)
                v = ((const float4*)x)[(size_t)grow * (IN_CH / 4) + kt * 8 + cc];
            ((float4*)&xs[r][0])[cc] = v;
        }
        // W tile: 32 rows x 32 float4
        for (int i = tid; i < BK * (IN_CH / 4); i += 256) {
            int kr = i >> 5;
            int cc = i & 31;
            ((float4*)&ws[kr][0])[cc] =
                ((const float4*)W)[(size_t)(kt * BK + kr) * (IN_CH / 4) + cc];
        }
        __syncthreads();
#pragma unroll 8
        for (int k = 0; k < BK; k++) {
            float4 wa = ((const float4*)&ws[k][0])[tx];        // cols 4tx..+3
            float4 wb = ((const float4*)&ws[k][0])[16 + tx];   // cols 64+4tx..+3
            unsigned long long wp[4];
            asm("mov.b64 %0, {%1, %2};" : "=l"(wp[0]) : "f"(wa.x), "f"(wa.y));
            asm("mov.b64 %0, {%1, %2};" : "=l"(wp[1]) : "f"(wa.z), "f"(wa.w));
            asm("mov.b64 %0, {%1, %2};" : "=l"(wp[2]) : "f"(wb.x), "f"(wb.y));
            asm("mov.b64 %0, {%1, %2};" : "=l"(wp[3]) : "f"(wb.z), "f"(wb.w));
#pragma unroll
            for (int i = 0; i < 8; i++) {
                float xv = xs[ty * 8 + i][k];
                unsigned long long xp;
                asm("mov.b64 %0, {%1, %1};" : "=l"(xp) : "f"(xv));
                asm("fma.rn.f32x2 %0, %1, %2, %0;" : "+l"(acc[i][0]) : "l"(xp), "l"(wp[0]));
                asm("fma.rn.f32x2 %0, %1, %2, %0;" : "+l"(acc[i][1]) : "l"(xp), "l"(wp[1]));
                asm("fma.rn.f32x2 %0, %1, %2, %0;" : "+l"(acc[i][2]) : "l"(xp), "l"(wp[2]));
                asm("fma.rn.f32x2 %0, %1, %2, %0;" : "+l"(acc[i][3]) : "l"(xp), "l"(wp[3]));
            }
        }
        __syncthreads();
    }

    // epilogue: fp16 h store + fused per-head scores (fp32)
#pragma unroll
    for (int i = 0; i < 8; i++) {
        int grow = row0 + ty * 8 + i;
        float c[8];
#pragma unroll
        for (int j = 0; j < 4; j++) {
            float lo, hi;
            asm("mov.b64 {%0, %1}, %2;" : "=f"(lo), "=f"(hi) : "l"(acc[i][j]));
            c[j * 2] = lo;
            c[j * 2 + 1] = hi;
        }
        if (grow < N_NODES) {
            uint2 pa, pb;
            __half2 t0 = __float22half2_rn(make_float2(c[0], c[1]));
            __half2 t1 = __float22half2_rn(make_float2(c[2], c[3]));
            __half2 t2 = __float22half2_rn(make_float2(c[4], c[5]));
            __half2 t3 = __float22half2_rn(make_float2(c[6], c[7]));
            pa.x = *(unsigned int*)&t0; pa.y = *(unsigned int*)&t1;
            pb.x = *(unsigned int*)&t2; pb.y = *(unsigned int*)&t3;
            ((uint2*)g_h16)[(size_t)grow * 32 + tx] = pa;
            ((uint2*)g_h16)[(size_t)grow * 32 + 16 + tx] = pb;
        }
        float ps0 = c[0] * as0[0] + c[1] * as0[1] + c[2] * as0[2] + c[3] * as0[3];
        float pt0 = c[0] * at0[0] + c[1] * at0[1] + c[2] * at0[2] + c[3] * at0[3];
        float ps1 = c[4] * as1[0] + c[5] * as1[1] + c[6] * as1[2] + c[7] * as1[3];
        float pt1 = c[4] * at1[0] + c[5] * at1[1] + c[6] * at1[2] + c[7] * at1[3];
#pragma unroll
        for (int off = 4; off > 0; off >>= 1) {
            ps0 += __shfl_xor_sync(0xffffffffu, ps0, off);
            pt0 += __shfl_xor_sync(0xffffffffu, pt0, off);
            ps1 += __shfl_xor_sync(0xffffffffu, ps1, off);
            pt1 += __shfl_xor_sync(0xffffffffu, pt1, off);
        }
        if ((tx & 7) == 0 && grow < N_NODES) {
            g_ssrc[grow * HEADS + h0] = ps0;
            g_stgt[grow * HEADS + h0] = pt0;
            g_ssrc[grow * HEADS + h0 + 2] = ps1;
            g_stgt[grow * HEADS + h0 + 2] = pt1;
        }
    }
}

// ---------------- gather-reduce: warp per node, fp16 h, fused finalize ----------------
__global__ __launch_bounds__(256) void gather_kernel(
    float* __restrict__ out, const float* __restrict__ bias) {
    int node = (blockIdx.x * blockDim.x + threadIdx.x) >> 5;
    int lane = threadIdx.x & 31;
    if (node >= N_NODES) return;
    int head = lane >> 3;

    int start = g_off[node];
    int cnt = g_deg[node];
    float st = g_stgt[node * HEADS + head];

    float4 acc = make_float4(0.f, 0.f, 0.f, 0.f);
    float den = 0.f;

    const uint2* h16 = (const uint2*)g_h16;
    int j = 0;
    for (; j + 2 <= cnt; j += 2) {
        int s0 = g_esrc[start + j];
        int s1 = g_esrc[start + j + 1];
        float sc0 = g_ssrc[s0 * HEADS + head] + st;
        float sc1 = g_ssrc[s1 * HEADS + head] + st;
        uint2 v0 = h16[(size_t)s0 * 32 + lane];
        uint2 v1 = h16[(size_t)s1 * 32 + lane];
        float lr0 = sc0 > 0.f ? sc0 : NEG_SLOPE * sc0;
        float lr1 = sc1 > 0.f ? sc1 : NEG_SLOPE * sc1;
        float w0 = __expf(-lr0);
        float w1 = __expf(-lr1);
        float2 a0 = __half22float2(*(const __half2*)&v0.x);
        float2 b0 = __half22float2(*(const __half2*)&v0.y);
        float2 a1 = __half22float2(*(const __half2*)&v1.x);
        float2 b1 = __half22float2(*(const __half2*)&v1.y);
        acc.x += w0 * a0.x + w1 * a1.x;
        acc.y += w0 * a0.y + w1 * a1.y;
        acc.z += w0 * b0.x + w1 * b1.x;
        acc.w += w0 * b0.y + w1 * b1.y;
        den += w0 + w1;
    }
    if (j < cnt) {
        int s0 = g_esrc[start + j];
        float sc0 = g_ssrc[s0 * HEADS + head] + st;
        uint2 v0 = h16[(size_t)s0 * 32 + lane];
        float lr0 = sc0 > 0.f ? sc0 : NEG_SLOPE * sc0;
        float w0 = __expf(-lr0);
        float2 a0 = __half22float2(*(const __half2*)&v0.x);
        float2 b0 = __half22float2(*(const __half2*)&v0.y);
        acc.x += w0 * a0.x;
        acc.y += w0 * a0.y;
        acc.z += w0 * b0.x;
        acc.w += w0 * b0.y;
        den += w0;
    }

    float d = den > EPS ? den : EPS;
    float inv = 1.0f / d;
    float4 b = ((const float4*)bias)[lane];
    float4 o;
    o.x = acc.x * inv + b.x;
    o.y = acc.y * inv + b.y;
    o.z = acc.z * inv + b.z;
    o.w = acc.w * inv + b.w;
    ((float4*)(out + (size_t)node * HO))[lane] = o;
}

extern "C" void kernel_launch(void* const* d_in, const int* in_sizes, int n_in,
                              void* d_out, int out_size) {
    const float* x = (const float*)d_in[0];
    const void* eidx = d_in[1];
    const float* W = (const float*)d_in[2];
    const float* att = (const float*)d_in[3];
    const float* bias = (const float*)d_in[4];
    float* out = (float*)d_out;

    detect_kernel<<<1, 256>>>((const unsigned int*)eidx);
    zero_deg_kernel<<<(N_NODES + 255) / 256, 256>>>();
    hist_kernel<<<(N_EDGES + 255) / 256, 256>>>(eidx);
    scan1_kernel<<<SCAN_NB, SCAN_B>>>();
    scan2_kernel<<<1, 256>>>();
    scan3_kernel<<<SCAN_NB, SCAN_B>>>();
    scatter_kernel<<<(N_EDGES + 255) / 256, 256>>>(eidx);
    gemm_kernel<<<(N_NODES + BM - 1) / BM, 256>>>(x, W, att);
    gather_kernel<<<(N_NODES * 32 + 255) / 256, 256>>>(out, bias);
}

// round 5
// speedup vs baseline: 1.1253x; 1.1253x over previous
#include <cuda_runtime.h>
#include <cuda_bf16.h>
#include <cuda_fp16.h>

#define N_NODES 100000
#define N_EDGES 1600000
#define IN_CH 128
#define HEADS 4
#define OUT_CH 32
#define HO 128
#define NEG_SLOPE 0.2f
#define EPS 1e-10f

#define SCAN_B 512
#define SCAN_NB ((N_NODES + SCAN_B - 1) / SCAN_B)   // 196

// ---------------- scratch ----------------
__device__ __align__(16) __half g_h16[(size_t)N_NODES * HO];   // 25.6 MB
__device__ __align__(16) float g_ssrc[(size_t)N_NODES * HEADS];
__device__ __align__(16) float g_stgt[(size_t)N_NODES * HEADS];
__device__ int g_deg[N_NODES];
__device__ int g_off[N_NODES];
__device__ int g_cursor[N_NODES];
__device__ int g_bsum[SCAN_NB];
__device__ int g_esrc[N_EDGES];
__device__ int g_idx64;

// ---------------- dtype detection for edge_index ----------------
__global__ void detect_kernel(const unsigned int* __restrict__ e) {
    __shared__ int any;
    if (threadIdx.x == 0) any = 0;
    __syncthreads();
    unsigned int v = 0;
    for (int i = threadIdx.x; i < 1024; i += blockDim.x) v |= e[2 * i + 1];
    if (v) any = 1;
    __syncthreads();
    if (threadIdx.x == 0) g_idx64 = (any == 0) ? 1 : 0;
}

__device__ __forceinline__ int load_idx(const void* eidx, int i) {
    if (g_idx64) return (int)((const long long*)eidx)[i];
    return ((const int*)eidx)[i];
}

__global__ void zero_deg_kernel() {
    int i = blockIdx.x * blockDim.x + threadIdx.x;
    if (i < N_NODES) g_deg[i] = 0;
}

__global__ __launch_bounds__(256) void hist_kernel(const void* __restrict__ eidx) {
    int e = blockIdx.x * blockDim.x + threadIdx.x;
    if (e >= N_EDGES) return;
    int tgt = load_idx(eidx, N_EDGES + e);
    atomicAdd(&g_deg[tgt], 1);
}

// ---------------- 3-phase exclusive scan of g_deg -> g_off ----------------
__global__ __launch_bounds__(SCAN_B) void scan1_kernel() {
    __shared__ int sm[SCAN_B];
    int i = blockIdx.x * SCAN_B + threadIdx.x;
    int t = threadIdx.x;
    int v = (i < N_NODES) ? g_deg[i] : 0;
    sm[t] = v;
    __syncthreads();
#pragma unroll
    for (int off = 1; off < SCAN_B; off <<= 1) {
        int a = (t >= off) ? sm[t - off] : 0;
        __syncthreads();
        sm[t] += a;
        __syncthreads();
    }
    if (i < N_NODES) g_off[i] = sm[t] - v;
    if (t == SCAN_B - 1) g_bsum[blockIdx.x] = sm[t];
}

__global__ __launch_bounds__(256) void scan2_kernel() {
    __shared__ int sm[256];
    int t = threadIdx.x;
    int v = (t < SCAN_NB) ? g_bsum[t] : 0;
    sm[t] = v;
    __syncthreads();
#pragma unroll
    for (int off = 1; off < 256; off <<= 1) {
        int a = (t >= off) ? sm[t - off] : 0;
        __syncthreads();
        sm[t] += a;
        __syncthreads();
    }
    if (t < SCAN_NB) g_bsum[t] = sm[t] - v;
}

__global__ __launch_bounds__(SCAN_B) void scan3_kernel() {
    int i = blockIdx.x * SCAN_B + threadIdx.x;
    if (i >= N_NODES) return;
    int o = g_off[i] + g_bsum[blockIdx.x];
    g_off[i] = o;
    g_cursor[i] = o;
}

__global__ __launch_bounds__(256) void scatter_kernel(const void* __restrict__ eidx) {
    int e = blockIdx.x * blockDim.x + threadIdx.x;
    if (e >= N_EDGES) return;
    int src = load_idx(eidx, e);
    int tgt = load_idx(eidx, N_EDGES + e);
    int slot = atomicAdd(&g_cursor[tgt], 1);
    g_esrc[slot] = src;
}

// ---------------- fused GEMM + score kernel (proven R3 tile) ----------------
// BM=64, 256 threads. Thread (tx=tid&31, ty=tid>>5): rows ty*8..+7, cols 4tx..+3.
// xs stored as duplicated pairs {v,v} -> LDS.64 gives packed broadcast operand.
#define BM 64
#define BK 32
__global__ __launch_bounds__(256) void gemm_kernel(
    const float* __restrict__ x, const float* __restrict__ W,
    const float* __restrict__ att) {
    __shared__ float2 xs2[BM][BK];    // 16 KB
    __shared__ float ws[BK][IN_CH];   // 16 KB
    const int tid = threadIdx.x;
    const int tx = tid & 31;
    const int ty = tid >> 5;
    const int row0 = blockIdx.x * BM;

    const int head = tx >> 3;
    const int o0 = (tx & 7) * 4;
    const float* arow = att + head * (2 * OUT_CH);
    float as0 = arow[o0], as1 = arow[o0 + 1], as2 = arow[o0 + 2], as3 = arow[o0 + 3];
    float at0 = arow[OUT_CH + o0], at1 = arow[OUT_CH + o0 + 1],
          at2 = arow[OUT_CH + o0 + 2], at3 = arow[OUT_CH + o0 + 3];

    unsigned long long acc[8][2];
#pragma unroll
    for (int i = 0; i < 8; i++) { acc[i][0] = 0ull; acc[i][1] = 0ull; }

    for (int kt = 0; kt < IN_CH / BK; kt++) {
        for (int i = tid; i < BM * (BK / 4); i += 256) {
            int r = i >> 3;
            int c4 = (i & 7) * 4;
            int grow = row0 + r;
            float4 v = make_float4(0.f, 0.f, 0.f, 0.f);
            if (grow < N_NODES)
                v = ((const float4*)x)[(size_t)grow * (IN_CH / 4) + kt * 8 + (i & 7)];
            xs2[r][c4 + 0] = make_float2(v.x, v.x);
            xs2[r][c4 + 1] = make_float2(v.y, v.y);
            xs2[r][c4 + 2] = make_float2(v.z, v.z);
            xs2[r][c4 + 3] = make_float2(v.w, v.w);
        }
        for (int i = tid; i < BK * (IN_CH / 4); i += 256) {
            int kr = i >> 5;
            int c4 = i & 31;
            ((float4*)&ws[kr][0])[c4] =
                ((const float4*)W)[(size_t)(kt * BK + kr) * (IN_CH / 4) + c4];
        }
        __syncthreads();
#pragma unroll
        for (int k = 0; k < BK; k++) {
            float4 w4 = ((const float4*)&ws[k][0])[tx];
            unsigned long long w01, w23;
            asm("mov.b64 %0, {%1, %2};" : "=l"(w01) : "f"(w4.x), "f"(w4.y));
            asm("mov.b64 %0, {%1, %2};" : "=l"(w23) : "f"(w4.z), "f"(w4.w));
#pragma unroll
            for (int i = 0; i < 8; i++) {
                unsigned long long xv2 =
                    *reinterpret_cast<const unsigned long long*>(&xs2[ty * 8 + i][k]);
                asm("fma.rn.f32x2 %0, %1, %2, %0;" : "+l"(acc[i][0]) : "l"(xv2), "l"(w01));
                asm("fma.rn.f32x2 %0, %1, %2, %0;" : "+l"(acc[i][1]) : "l"(xv2), "l"(w23));
            }
        }
        __syncthreads();
    }

    // epilogue: fp16 h store + fused per-head scores (fp32)
#pragma unroll
    for (int i = 0; i < 8; i++) {
        int grow = row0 + ty * 8 + i;
        float c0, c1, c2, c3;
        asm("mov.b64 {%0, %1}, %2;" : "=f"(c0), "=f"(c1) : "l"(acc[i][0]));
        asm("mov.b64 {%0, %1}, %2;" : "=f"(c2), "=f"(c3) : "l"(acc[i][1]));
        if (grow < N_NODES) {
            __half2 t0 = __float22half2_rn(make_float2(c0, c1));
            __half2 t1 = __float22half2_rn(make_float2(c2, c3));
            uint2 p;
            p.x = *(unsigned int*)&t0;
            p.y = *(unsigned int*)&t1;
            ((uint2*)g_h16)[(size_t)grow * 32 + tx] = p;
        }
        float ps = c0 * as0 + c1 * as1 + c2 * as2 + c3 * as3;
        float pt = c0 * at0 + c1 * at1 + c2 * at2 + c3 * at3;
#pragma unroll
        for (int off = 4; off > 0; off >>= 1) {
            ps += __shfl_xor_sync(0xffffffffu, ps, off);
            pt += __shfl_xor_sync(0xffffffffu, pt, off);
        }
        if ((tx & 7) == 0 && grow < N_NODES) {
            g_ssrc[grow * HEADS + head] = ps;
            g_stgt[grow * HEADS + head] = pt;
        }
    }
}

// ---------------- gather-reduce: warp per node, fp16 h, fused finalize ----------------
__global__ __launch_bounds__(256) void gather_kernel(
    float* __restrict__ out, const float* __restrict__ bias) {
    int node = (blockIdx.x * blockDim.x + threadIdx.x) >> 5;
    int lane = threadIdx.x & 31;
    if (node >= N_NODES) return;
    int head = lane >> 3;

    int start = g_off[node];
    int cnt = g_deg[node];
    float st = g_stgt[node * HEADS + head];

    float4 acc = make_float4(0.f, 0.f, 0.f, 0.f);
    float den = 0.f;

    const uint2* h16 = (const uint2*)g_h16;
    int j = 0;
    for (; j + 2 <= cnt; j += 2) {
        int s0 = g_esrc[start + j];
        int s1 = g_esrc[start + j + 1];
        float sc0 = g_ssrc[s0 * HEADS + head] + st;
        float sc1 = g_ssrc[s1 * HEADS + head] + st;
        uint2 v0 = h16[(size_t)s0 * 32 + lane];
        uint2 v1 = h16[(size_t)s1 * 32 + lane];
        float lr0 = sc0 > 0.f ? sc0 : NEG_SLOPE * sc0;
        float lr1 = sc1 > 0.f ? sc1 : NEG_SLOPE * sc1;
        float w0 = __expf(-lr0);
        float w1 = __expf(-lr1);
        float2 a0 = __half22float2(*(const __half2*)&v0.x);
        float2 b0 = __half22float2(*(const __half2*)&v0.y);
        float2 a1 = __half22float2(*(const __half2*)&v1.x);
        float2 b1 = __half22float2(*(const __half2*)&v1.y);
        acc.x += w0 * a0.x + w1 * a1.x;
        acc.y += w0 * a0.y + w1 * a1.y;
        acc.z += w0 * b0.x + w1 * b1.x;
        acc.w += w0 * b0.y + w1 * b1.y;
        den += w0 + w1;
    }
    if (j < cnt) {
        int s0 = g_esrc[start + j];
        float sc0 = g_ssrc[s0 * HEADS + head] + st;
        uint2 v0 = h16[(size_t)s0 * 32 + lane];
        float lr0 = sc0 > 0.f ? sc0 : NEG_SLOPE * sc0;
        float w0 = __expf(-lr0);
        float2 a0 = __half22float2(*(const __half2*)&v0.x);
        float2 b0 = __half22float2(*(const __half2*)&v0.y);
        acc.x += w0 * a0.x;
        acc.y += w0 * a0.y;
        acc.z += w0 * b0.x;
        acc.w += w0 * b0.y;
        den += w0;
    }

    float d = den > EPS ? den : EPS;
    float inv = 1.0f / d;
    float4 b = ((const float4*)bias)[lane];
    float4 o;
    o.x = acc.x * inv + b.x;
    o.y = acc.y * inv + b.y;
    o.z = acc.z * inv + b.z;
    o.w = acc.w * inv + b.w;
    ((float4*)(out + (size_t)node * HO))[lane] = o;
}

extern "C" void kernel_launch(void* const* d_in, const int* in_sizes, int n_in,
                              void* d_out, int out_size) {
    const float* x = (const float*)d_in[0];
    const void* eidx = d_in[1];
    const float* W = (const float*)d_in[2];
    const float* att = (const float*)d_in[3];
    const float* bias = (const float*)d_in[4];
    float* out = (float*)d_out;

    detect_kernel<<<1, 256>>>((const unsigned int*)eidx);
    zero_deg_kernel<<<(N_NODES + 255) / 256, 256>>>();
    hist_kernel<<<(N_EDGES + 255) / 256, 256>>>(eidx);
    scan1_kernel<<<SCAN_NB, SCAN_B>>>();
    scan2_kernel<<<1, 256>>>();
    scan3_kernel<<<SCAN_NB, SCAN_B>>>();
    scatter_kernel<<<(N_EDGES + 255) / 256, 256>>>(eidx);
    gemm_kernel<<<(N_NODES + BM - 1) / BM, 256>>>(x, W, att);
    gather_kernel<<<(N_NODES * 32 + 255) / 256, 256>>>(out, bias);
}

// round 7
// speedup vs baseline: 1.8555x; 1.6488x over previous
#include <cuda_runtime.h>
#include <cuda_bf16.h>
#include <cuda_fp16.h>
#include <cstdint>

#define N_NODES 100000
#define N_EDGES 1600000
#define IN_CH 128
#define HEADS 4
#define OUT_CH 32
#define HO 128
#define NEG_SLOPE 0.2f
#define EPS 1e-10f

#define SCAN_B 512
#define SCAN_NB ((N_NODES + SCAN_B - 1) / SCAN_B)   // 196

// ---------------- scratch ----------------
__device__ __align__(16) __half g_h16[(size_t)N_NODES * HO];   // 25.6 MB
__device__ __align__(16) float g_ssrc[(size_t)N_NODES * HEADS];
__device__ __align__(16) float g_stgt[(size_t)N_NODES * HEADS];
__device__ __align__(16) __half g_wt16[IN_CH * HO];            // W^T fp16 [n][k]
__device__ int g_deg[N_NODES];
__device__ int g_off[N_NODES];
__device__ int g_cursor[N_NODES];
__device__ int g_bsum[SCAN_NB];
__device__ int g_esrc[N_EDGES];
__device__ int g_idx64;

// ---------------- dtype detection for edge_index ----------------
__global__ void detect_kernel(const unsigned int* __restrict__ e) {
    __shared__ int any;
    if (threadIdx.x == 0) any = 0;
    __syncthreads();
    unsigned int v = 0;
    for (int i = threadIdx.x; i < 1024; i += blockDim.x) v |= e[2 * i + 1];
    if (v) any = 1;
    __syncthreads();
    if (threadIdx.x == 0) g_idx64 = (any == 0) ? 1 : 0;
}

__device__ __forceinline__ int load_idx(const void* eidx, int i) {
    if (g_idx64) return (int)((const long long*)eidx)[i];
    return ((const int*)eidx)[i];
}

__global__ void zero_deg_kernel() {
    int i = blockIdx.x * blockDim.x + threadIdx.x;
    if (i < N_NODES) g_deg[i] = 0;
}

__global__ __launch_bounds__(256) void hist_kernel(const void* __restrict__ eidx) {
    int e = blockIdx.x * blockDim.x + threadIdx.x;
    if (e >= N_EDGES) return;
    int tgt = load_idx(eidx, N_EDGES + e);
    atomicAdd(&g_deg[tgt], 1);
}

// ---------------- 3-phase exclusive scan of g_deg -> g_off ----------------
__global__ __launch_bounds__(SCAN_B) void scan1_kernel() {
    __shared__ int sm[SCAN_B];
    int i = blockIdx.x * SCAN_B + threadIdx.x;
    int t = threadIdx.x;
    int v = (i < N_NODES) ? g_deg[i] : 0;
    sm[t] = v;
    __syncthreads();
#pragma unroll
    for (int off = 1; off < SCAN_B; off <<= 1) {
        int a = (t >= off) ? sm[t - off] : 0;
        __syncthreads();
        sm[t] += a;
        __syncthreads();
    }
    if (i < N_NODES) g_off[i] = sm[t] - v;
    if (t == SCAN_B - 1) g_bsum[blockIdx.x] = sm[t];
}

__global__ __launch_bounds__(256) void scan2_kernel() {
    __shared__ int sm[256];
    int t = threadIdx.x;
    int v = (t < SCAN_NB) ? g_bsum[t] : 0;
    sm[t] = v;
    __syncthreads();
#pragma unroll
    for (int off = 1; off < 256; off <<= 1) {
        int a = (t >= off) ? sm[t - off] : 0;
        __syncthreads();
        sm[t] += a;
        __syncthreads();
    }
    if (t < SCAN_NB) g_bsum[t] = sm[t] - v;
}

__global__ __launch_bounds__(SCAN_B) void scan3_kernel() {
    int i = blockIdx.x * SCAN_B + threadIdx.x;
    if (i >= N_NODES) return;
    int o = g_off[i] + g_bsum[blockIdx.x];
    g_off[i] = o;
    g_cursor[i] = o;
}

__global__ __launch_bounds__(256) void scatter_kernel(const void* __restrict__ eidx) {
    int e = blockIdx.x * blockDim.x + threadIdx.x;
    if (e >= N_EDGES) return;
    int src = load_idx(eidx, e);
    int tgt = load_idx(eidx, N_EDGES + e);
    int slot = atomicAdd(&g_cursor[tgt], 1);
    g_esrc[slot] = src;
}

// ---------------- W prep: g_wt16[n][k] = fp16(W[k][n]) ----------------
__global__ __launch_bounds__(256) void wprep_kernel(const float* __restrict__ W) {
    int i = blockIdx.x * blockDim.x + threadIdx.x;
    if (i >= IN_CH * HO) return;
    int n = i & 127;
    int k = i >> 7;
    g_wt16[n * IN_CH + k] = __float2half(W[k * HO + n]);
}

// ---------------- HMMA GEMM + fused scores ----------------
// Per CTA: 64 rows, 4 warps, each warp 16 rows x 128 cols via
// mma.sync.m16n8k16 (fp16 in, fp32 acc). A/B in smem, stride 136 halves.
#define A_STRIDE 136
#define W_STRIDE 136
#define ACC_STRIDE 132
#define SMEM_A_BYTES (64 * A_STRIDE * 2)            // 17408
#define SMEM_W_BYTES (128 * W_STRIDE * 2)           // 34816
#define SMEM_TOTAL (SMEM_A_BYTES + SMEM_W_BYTES)    // 52224

extern __shared__ char dsm[];

__global__ __launch_bounds__(128) void gemm_kernel(
    const float* __restrict__ x, const float* __restrict__ att) {
    __shared__ float s_att[HEADS * 2 * OUT_CH];     // 256

    const int tid = threadIdx.x;
    const int warpid = tid >> 5;
    const int lane = tid & 31;
    const int g = lane >> 2;        // group row
    const int tg = lane & 3;        // thread-in-group
    const int row0 = blockIdx.x * 64;

    __half* As = (__half*)dsm;
    __half* Ws = (__half*)(dsm + SMEM_A_BYTES);

    s_att[tid] = att[tid];
    s_att[tid + 128] = att[tid + 128];

    // copy W^T fp16 into padded smem: 2048 uint4 (8 halves each)
    {
        const uint4* wsrc = (const uint4*)g_wt16;
#pragma unroll
        for (int j = 0; j < 16; j++) {
            int i = tid + j * 128;
            int row = i >> 4;
            int c8 = i & 15;
            *(uint4*)&Ws[row * W_STRIDE + c8 * 8] = wsrc[i];
        }
    }

    // load x fp32 -> fp16 into padded smem: 64 rows x 32 float4
    {
#pragma unroll
        for (int j = 0; j < 16; j++) {
            int i = tid + j * 128;
            int row = i >> 5;
            int c4 = i & 31;
            int grow = row0 + row;
            float4 v = make_float4(0.f, 0.f, 0.f, 0.f);
            if (grow < N_NODES)
                v = ((const float4*)x)[(size_t)grow * (IN_CH / 4) + c4];
            __half2 h0 = __float22half2_rn(make_float2(v.x, v.y));
            __half2 h1 = __float22half2_rn(make_float2(v.z, v.w));
            uint2 p;
            p.x = *(unsigned int*)&h0;
            p.y = *(unsigned int*)&h1;
            *(uint2*)&As[row * A_STRIDE + c4 * 4] = p;
        }
    }
    __syncthreads();

    float acc[16][4];
#pragma unroll
    for (int nt = 0; nt < 16; nt++)
#pragma unroll
        for (int j = 0; j < 4; j++) acc[nt][j] = 0.f;

    const int arow = warpid * 16 + g;
#pragma unroll
    for (int ks = 0; ks < 8; ks++) {
        int kcol = ks * 16 + tg * 2;
        uint32_t a0 = *(uint32_t*)&As[arow * A_STRIDE + kcol];
        uint32_t a1 = *(uint32_t*)&As[(arow + 8) * A_STRIDE + kcol];
        uint32_t a2 = *(uint32_t*)&As[arow * A_STRIDE + kcol + 8];
        uint32_t a3 = *(uint32_t*)&As[(arow + 8) * A_STRIDE + kcol + 8];
#pragma unroll
        for (int nt = 0; nt < 16; nt++) {
            int n = nt * 8 + g;
            uint32_t b0 = *(uint32_t*)&Ws[n * W_STRIDE + kcol];
            uint32_t b1 = *(uint32_t*)&Ws[n * W_STRIDE + kcol + 8];
            asm volatile(
                "mma.sync.aligned.m16n8k16.row.col.f32.f16.f16.f32 "
                "{%0,%1,%2,%3}, {%4,%5,%6,%7}, {%8,%9}, {%0,%1,%2,%3};"
                : "+f"(acc[nt][0]), "+f"(acc[nt][1]),
                  "+f"(acc[nt][2]), "+f"(acc[nt][3])
                : "r"(a0), "r"(a1), "r"(a2), "r"(a3), "r"(b0), "r"(b1));
        }
    }
    __syncthreads();   // Ws reads done everywhere; reuse smem for fp32 staging

    // stage accs: sAcc[64][ACC_STRIDE] fp32 (spans As+Ws regions)
    float* sAcc = (float*)dsm;
    {
        int r0 = warpid * 16 + g;
#pragma unroll
        for (int nt = 0; nt < 16; nt++) {
            int col = nt * 8 + tg * 2;
            *(float2*)&sAcc[r0 * ACC_STRIDE + col] =
                make_float2(acc[nt][0], acc[nt][1]);
            *(float2*)&sAcc[(r0 + 8) * ACC_STRIDE + col] =
                make_float2(acc[nt][2], acc[nt][3]);
        }
    }
    __syncwarp();

    // R3-style epilogue: warp handles its own 16 rows
    const int head = lane >> 3;
    const int o0 = (lane & 7) * 4;
    float as0 = s_att[head * 64 + o0], as1 = s_att[head * 64 + o0 + 1],
          as2 = s_att[head * 64 + o0 + 2], as3 = s_att[head * 64 + o0 + 3];
    float at0 = s_att[head * 64 + 32 + o0], at1 = s_att[head * 64 + 32 + o0 + 1],
          at2 = s_att[head * 64 + 32 + o0 + 2], at3 = s_att[head * 64 + 32 + o0 + 3];

#pragma unroll
    for (int rr = 0; rr < 16; rr++) {
        int row = warpid * 16 + rr;
        int grow = row0 + row;
        float4 c = *(float4*)&sAcc[row * ACC_STRIDE + lane * 4];
        if (grow < N_NODES) {
            __half2 t0 = __float22half2_rn(make_float2(c.x, c.y));
            __half2 t1 = __float22half2_rn(make_float2(c.z, c.w));
            uint2 p;
            p.x = *(unsigned int*)&t0;
            p.y = *(unsigned int*)&t1;
            ((uint2*)(g_h16 + (size_t)grow * HO))[lane] = p;
        }
        float ps = c.x * as0 + c.y * as1 + c.z * as2 + c.w * as3;
        float pt = c.x * at0 + c.y * at1 + c.z * at2 + c.w * at3;
#pragma unroll
        for (int off = 4; off > 0; off >>= 1) {
            ps += __shfl_xor_sync(0xffffffffu, ps, off);
            pt += __shfl_xor_sync(0xffffffffu, pt, off);
        }
        if ((lane & 7) == 0 && grow < N_NODES) {
            g_ssrc[grow * HEADS + head] = ps;
            g_stgt[grow * HEADS + head] = pt;
        }
    }
}

// ---------------- gather-reduce: warp per node, fp16 h, fused finalize ----------------
__global__ __launch_bounds__(256) void gather_kernel(
    float* __restrict__ out, const float* __restrict__ bias) {
    int node = (blockIdx.x * blockDim.x + threadIdx.x) >> 5;
    int lane = threadIdx.x & 31;
    if (node >= N_NODES) return;
    int head = lane >> 3;

    int start = g_off[node];
    int cnt = g_deg[node];
    float st = g_stgt[node * HEADS + head];

    float4 acc = make_float4(0.f, 0.f, 0.f, 0.f);
    float den = 0.f;

    const uint2* h16 = (const uint2*)g_h16;
    int j = 0;
    for (; j + 2 <= cnt; j += 2) {
        int s0 = g_esrc[start + j];
        int s1 = g_esrc[start + j + 1];
        float sc0 = g_ssrc[s0 * HEADS + head] + st;
        float sc1 = g_ssrc[s1 * HEADS + head] + st;
        uint2 v0 = h16[(size_t)s0 * 32 + lane];
        uint2 v1 = h16[(size_t)s1 * 32 + lane];
        float lr0 = sc0 > 0.f ? sc0 : NEG_SLOPE * sc0;
        float lr1 = sc1 > 0.f ? sc1 : NEG_SLOPE * sc1;
        float w0 = __expf(-lr0);
        float w1 = __expf(-lr1);
        float2 a0 = __half22float2(*(const __half2*)&v0.x);
        float2 b0 = __half22float2(*(const __half2*)&v0.y);
        float2 a1 = __half22float2(*(const __half2*)&v1.x);
        float2 b1 = __half22float2(*(const __half2*)&v1.y);
        acc.x += w0 * a0.x + w1 * a1.x;
        acc.y += w0 * a0.y + w1 * a1.y;
        acc.z += w0 * b0.x + w1 * b1.x;
        acc.w += w0 * b0.y + w1 * b1.y;
        den += w0 + w1;
    }
    if (j < cnt) {
        int s0 = g_esrc[start + j];
        float sc0 = g_ssrc[s0 * HEADS + head] + st;
        uint2 v0 = h16[(size_t)s0 * 32 + lane];
        float lr0 = sc0 > 0.f ? sc0 : NEG_SLOPE * sc0;
        float w0 = __expf(-lr0);
        float2 a0 = __half22float2(*(const __half2*)&v0.x);
        float2 b0 = __half22float2(*(const __half2*)&v0.y);
        acc.x += w0 * a0.x;
        acc.y += w0 * a0.y;
        acc.z += w0 * b0.x;
        acc.w += w0 * b0.y;
        den += w0;
    }

    float d = den > EPS ? den : EPS;
    float inv = 1.0f / d;
    float4 b = ((const float4*)bias)[lane];
    float4 o;
    o.x = acc.x * inv + b.x;
    o.y = acc.y * inv + b.y;
    o.z = acc.z * inv + b.z;
    o.w = acc.w * inv + b.w;
    ((float4*)(out + (size_t)node * HO))[lane] = o;
}

extern "C" void kernel_launch(void* const* d_in, const int* in_sizes, int n_in,
                              void* d_out, int out_size) {
    const float* x = (const float*)d_in[0];
    const void* eidx = d_in[1];
    const float* W = (const float*)d_in[2];
    const float* att = (const float*)d_in[3];
    const float* bias = (const float*)d_in[4];
    float* out = (float*)d_out;

    cudaFuncSetAttribute(gemm_kernel, cudaFuncAttributeMaxDynamicSharedMemorySize,
                         SMEM_TOTAL);

    detect_kernel<<<1, 256>>>((const unsigned int*)eidx);
    zero_deg_kernel<<<(N_NODES + 255) / 256, 256>>>();
    hist_kernel<<<(N_EDGES + 255) / 256, 256>>>(eidx);
    scan1_kernel<<<SCAN_NB, SCAN_B>>>();
    scan2_kernel<<<1, 256>>>();
    scan3_kernel<<<SCAN_NB, SCAN_B>>>();
    scatter_kernel<<<(N_EDGES + 255) / 256, 256>>>(eidx);
    wprep_kernel<<<(IN_CH * HO + 255) / 256, 256>>>(W);
    gemm_kernel<<<(N_NODES + 63) / 64, 128, SMEM_TOTAL>>>(x, att);
    gather_kernel<<<(N_NODES * 32 + 255) / 256, 256>>>(out, bias);
}